// round 14
// baseline (speedup 1.0000x reference)
#include <cuda_runtime.h>
#include <math.h>

#define BB 8
#define NN 256
#define DD 128
#define ROWS (BB*NN)          // 2048
#define EROWS (BB*NN*NN)      // 524288
#define BN_EPS 1e-5f
#define RPW 8                 // e-rows per warp in copy kernel
#define TI  4                 // i-rows per tail block
#define NB_TAIL (ROWS/TI)     // 512 tail blocks
#define NB_COPY  8192
#define NB_HW    64           // copy blocks 1..64 compute HW (32 rows each)

// __device__ globals (zero at load; stats/barrier re-zeroed by copy block 0
// every launch, stream-ordered before the tail -> graph-replay safe)
__device__ float  g_w[EROWS];
__device__ float4 g_hp[BB*(NN/4)*DD];  // packed HW: [b][j4][t] = HW[b,4j4..+3,t]
__device__ float  g_sum[DD];
__device__ float  g_sumsq[DD];
__device__ int    g_bar;

// ---------------------------------------------------------------------------
// Kernel 1: norm + copy of e (6.4 TB/s hot path untouched).
// Block 0: zero stats/barrier.
// Blocks 1..64: compute HW = h @ W^T (32 rows each) into packed layout.
//   HW[j][k] = sum_d h[j][d] * W[k][d].  Work hidden under the 75us stream.
// launch_bounds(256,5) caps regs ~51 so the copy hot path (40 regs) keeps
// its occupancy; any spill lands only in the hidden HW path.
// ---------------------------------------------------------------------------
__global__ void __launch_bounds__(256, 5) k_norm_copy(
    const float4* __restrict__ e,
    float4* __restrict__ out_e,
    const float* __restrict__ Wm,
    const float* __restrict__ h)
{
    if (blockIdx.x == 0) {
        if (threadIdx.x < DD) {
            g_sum[threadIdx.x]   = 0.0f;
            g_sumsq[threadIdx.x] = 0.0f;
            if (threadIdx.x == 0) g_bar = 0;
        }
    } else if (blockIdx.x <= NB_HW) {
        int m  = blockIdx.x - 1;            // 0..63
        int b  = m >> 3;                    // batch
        int jb = (m & 7) * 32;              // first row (within batch)
        int k  = threadIdx.x & 127;         // output feature
        int rg = threadIdx.x >> 7;          // row-group half: 16 rows
        int j0 = jb + rg * 16;

        const float4* hb4 = (const float4*)(h + (size_t)b * NN * DD);
        const float4* Wm4 = (const float4*)Wm;

        float acc[16];
        #pragma unroll
        for (int jj = 0; jj < 16; jj++) acc[jj] = 0.0f;

        for (int d4 = 0; d4 < DD/4; d4++) {
            float4 wv = Wm4[k * (DD/4) + d4];        // W[k][4d4..+3], L1-hot
            #pragma unroll
            for (int jj = 0; jj < 16; jj++) {
                float4 xv = hb4[(j0 + jj) * (DD/4) + d4];  // broadcast, L1-hot
                acc[jj] = fmaf(xv.x, wv.x, acc[jj]);
                acc[jj] = fmaf(xv.y, wv.y, acc[jj]);
                acc[jj] = fmaf(xv.z, wv.z, acc[jj]);
                acc[jj] = fmaf(xv.w, wv.w, acc[jj]);
            }
        }
        // write into packed layout: g_hp[b][j>>2][k] component (j&3)
        float* hp = (float*)(g_hp + (size_t)b * (NN/4) * DD);
        #pragma unroll
        for (int jj = 0; jj < 16; jj++) {
            int jr = j0 + jj;
            hp[(((jr >> 2) * DD) + k) * 4 + (jr & 3)] = acc[jj];
        }
    }

    size_t gw   = (size_t)((blockIdx.x * blockDim.x + threadIdx.x) >> 5);
    int    lane = threadIdx.x & 31;
    size_t r0i  = gw * RPW;
    size_t base = r0i * 32 + lane;

    float4 v[RPW];
    #pragma unroll
    for (int k = 0; k < RPW; k++)
        v[k] = __ldcs(e + base + (size_t)k * 32);
    #pragma unroll
    for (int k = 0; k < RPW; k++)
        __stcs(out_e + base + (size_t)k * 32, v[k]);

    float s[RPW];
    #pragma unroll
    for (int k = 0; k < RPW; k++)
        s[k] = v[k].x*v[k].x + v[k].y*v[k].y + v[k].z*v[k].z + v[k].w*v[k].w;
    #pragma unroll
    for (int o = 16; o > 0; o >>= 1) {
        #pragma unroll
        for (int k = 0; k < RPW; k++)
            s[k] += __shfl_xor_sync(0xffffffffu, s[k], o);
    }
    if (lane == 0) {
        #pragma unroll
        for (int k = 0; k < RPW; k++)
            g_w[r0i + k] = sqrtf(s[k]);
    }
}

// ---------------------------------------------------------------------------
// Kernel 2: tail (NO linear phase — algebraically folded into HW).
// 512 blocks x 256 threads, launch_bounds(256,4) => 4+ blocks/SM guaranteed
// (barrier safe). t = tid&127 (feature), half = tid>>7.
//   A: softmax (warps 0-3, float4 loads)
//   B: agg over packed HW — half owns 32 j4's for ALL 4 rows, MLP=8
//   C: y = relu(HW[i] + agg + bias); BN stats -> grid barrier -> BN apply
// ---------------------------------------------------------------------------
__global__ void __launch_bounds__(256, 4) k_tail(
    const float* __restrict__ h,
    const float* __restrict__ bias,
    const float* __restrict__ gamma,
    const float* __restrict__ beta,
    float* __restrict__ out_h)
{
    int bi0 = blockIdx.x * TI;
    int b   = bi0 >> 8;
    int i0  = bi0 & 255;
    int tid = threadIdx.x;
    int t    = tid & 127;
    int half = tid >> 7;
    int warp = tid >> 5, lane = tid & 31;

    __shared__ float sw[TI][NN];          // softmax probs (4 KB)
    __shared__ float spart[2][TI][DD];    // agg partials  (4 KB)
    __shared__ float pp[DD], pps[DD];     // BN partials   (1 KB)

    // --- A: softmax, warps 0-3 own one row each; float4 loads ---
    if (warp < TI) {
        const float4* wrow4 = (const float4*)(g_w + (size_t)(bi0 + warp) * NN);
        float4 a = wrow4[lane * 2];
        float4 c = wrow4[lane * 2 + 1];
        float m = fmaxf(fmaxf(fmaxf(a.x, a.y), fmaxf(a.z, a.w)),
                        fmaxf(fmaxf(c.x, c.y), fmaxf(c.z, c.w)));
        #pragma unroll
        for (int o = 16; o > 0; o >>= 1)
            m = fmaxf(m, __shfl_xor_sync(0xffffffffu, m, o));
        a.x = __expf(a.x - m); a.y = __expf(a.y - m);
        a.z = __expf(a.z - m); a.w = __expf(a.w - m);
        c.x = __expf(c.x - m); c.y = __expf(c.y - m);
        c.z = __expf(c.z - m); c.w = __expf(c.w - m);
        float sum = a.x + a.y + a.z + a.w + c.x + c.y + c.z + c.w;
        #pragma unroll
        for (int o = 16; o > 0; o >>= 1)
            sum += __shfl_xor_sync(0xffffffffu, sum, o);
        float inv = 1.0f / sum;
        a.x *= inv; a.y *= inv; a.z *= inv; a.w *= inv;
        c.x *= inv; c.y *= inv; c.z *= inv; c.w *= inv;
        float4* swr4 = (float4*)&sw[warp][0];
        swr4[lane * 2]     = a;
        swr4[lane * 2 + 1] = c;
    }
    __syncthreads();

    // --- B: agg over packed HW. half owns j4 in [32h, 32h+32); MLP=8 ---
    {
        const float4* hp = g_hp + (size_t)b * (NN/4) * DD;
        float acc[TI] = {0.f, 0.f, 0.f, 0.f};
        int j4b = half * 32;
        #pragma unroll
        for (int cch = 0; cch < 4; cch++) {
            float4 hv[8];
            #pragma unroll
            for (int k = 0; k < 8; k++)
                hv[k] = hp[(j4b + cch*8 + k) * DD + t];
            #pragma unroll
            for (int k = 0; k < 8; k++) {
                int j4 = j4b + cch*8 + k;
                #pragma unroll
                for (int r = 0; r < TI; r++) {
                    float4 p = *(const float4*)&sw[r][j4 * 4];  // broadcast
                    acc[r] = fmaf(p.x, hv[k].x, acc[r]);
                    acc[r] = fmaf(p.y, hv[k].y, acc[r]);
                    acc[r] = fmaf(p.z, hv[k].z, acc[r]);
                    acc[r] = fmaf(p.w, hv[k].w, acc[r]);
                }
            }
        }
        #pragma unroll
        for (int r = 0; r < TI; r++)
            spart[half][r][t] = acc[r];
    }
    __syncthreads();

    // --- C: y = relu(HW[i] + agg + bias); half owns rows {2h, 2h+1} ---
    const float* hb  = h + (size_t)b * NN * DD;
    const float* hpf = (const float*)(g_hp + (size_t)b * (NN/4) * DD);
    float y[2], hres[2];
    float bt = bias[t];
    float ls = 0.0f, lss = 0.0f;
    #pragma unroll
    for (int rr = 0; rr < 2; rr++) {
        int r   = half * 2 + rr;
        int row = i0 + r;
        hres[rr] = hb[row * DD + t];
        float hwown = hpf[(((row >> 2) * DD) + t) * 4 + (row & 3)];
        y[rr] = fmaxf(bt + hwown + spart[0][r][t] + spart[1][r][t], 0.0f);
        ls  += y[rr];
        lss  = fmaf(y[rr], y[rr], lss);
    }
    if (half == 1) { pp[t] = ls; pps[t] = lss; }
    __syncthreads();
    if (half == 0) {
        atomicAdd(&g_sum[t],   ls  + pp[t]);
        atomicAdd(&g_sumsq[t], lss + pps[t]);
    }

    // --- grid barrier (512 blocks co-resident by launch_bounds(256,4)) ---
    __syncthreads();
    if (tid == 0) {
        __threadfence();
        atomicAdd(&g_bar, 1);
        while (atomicAdd(&g_bar, 0) < NB_TAIL) __nanosleep(64);
    }
    __syncthreads();
    __threadfence();

    // --- BN apply + residual straight from registers ---
    float s  = __ldcg(&g_sum[t]);
    float ss = __ldcg(&g_sumsq[t]);
    float mean = s * (1.0f / ROWS);
    float var  = ss * (1.0f / ROWS) - mean * mean;
    float g  = gamma[t] * rsqrtf(var + BN_EPS);
    float b2 = beta[t] - mean * g;
    #pragma unroll
    for (int rr = 0; rr < 2; rr++) {
        int r = half * 2 + rr;
        out_h[(bi0 + r) * DD + t] = fmaf(y[rr], g, b2) + hres[rr];
    }
}

// ---------------------------------------------------------------------------
extern "C" void kernel_launch(void* const* d_in, const int* in_sizes, int n_in,
                              void* d_out, int out_size) {
    const float* h     = (const float*)d_in[0];   // (8,256,128)
    const float* e     = (const float*)d_in[1];   // (8,256,256,128)
    const float* Wm    = (const float*)d_in[2];   // (128,128)
    const float* bias  = (const float*)d_in[3];   // (128)
    const float* gamma = (const float*)d_in[4];   // (128)
    const float* beta  = (const float*)d_in[5];   // (128)

    float* out_h = (float*)d_out;                 // (8,256,128) first
    float* out_e = out_h + (size_t)ROWS * DD;     // then (8,256,256,128)

    k_norm_copy<<<NB_COPY, 256>>>((const float4*)e, (float4*)out_e, Wm, h);
    k_tail<<<NB_TAIL, 256>>>(h, bias, gamma, beta, out_h);
}